// round 11
// baseline (speedup 1.0000x reference)
#include <cuda_runtime.h>

// Problem constants (from reference: B=16, L=192, E=128, T=25)
#define BB   16
#define LL   192
#define EE   128
#define TT   25
#define NI   (LL - TT - 1)          // 166 block rows per batch (even)
#define LOUT (TT + 1 + NI * LL)     // 31898 output rows per batch
#define E4   (EE / 4)               // 32 float4 per row
#define G    2                      // i-values per CTA (166 % 2 == 0, no tail)
#define NZ   8                      // l-slices per (tile,b)
#define LCH  (LL / NZ)              // 24 l-values per slice

// s0 table: sigmoid(x*(W0-W1)+(b0-b1)). 1.5 MB, L2-resident.
__device__ __align__(16) float g_S[BB * LL * EE];

__device__ __forceinline__ float sigmoidf_fast(float z) {
    return __frcp_rn(1.0f + __expf(-z));
}

// Kernel 1 (producer): S table (float4-vectorized) + head copy.
// Triggers the dependent launch as soon as the S writes are fenced;
// the head-copy tail overlaps with the consumer's prologue.
__global__ void __launch_bounds__(256)
prep_kernel(const float* __restrict__ x,
            const float* __restrict__ W,
            const float* __restrict__ bvec,
            float* __restrict__ out) {
    const int idx = blockIdx.x * blockDim.x + threadIdx.x;   // 0..98303
    const float dw = W[0] - W[1];
    const float db = bvec[0] - bvec[1];

    const float4* __restrict__ x4 = reinterpret_cast<const float4*>(x);
    float4* __restrict__ S4 = reinterpret_cast<float4*>(g_S);

    float4 v = __ldg(&x4[idx]);
    float4 s;
    s.x = sigmoidf_fast(fmaf(v.x, dw, db));
    s.y = sigmoidf_fast(fmaf(v.y, dw, db));
    s.z = sigmoidf_fast(fmaf(v.z, dw, db));
    s.w = sigmoidf_fast(fmaf(v.w, dw, db));
    S4[idx] = s;

    __threadfence();
    cudaTriggerProgrammaticLaunchCompletion();

    // Head copy: out[:, :26, :] = x[:, :26, :]  (13312 float4s)
    if (idx < BB * (TT + 1) * E4) {
        int e = idx % E4;
        int t = (idx / E4) % (TT + 1);
        int b = idx / (E4 * (TT + 1));
        float4 h = __ldg(&x4[((size_t)b * LL + t) * E4 + e]);
        reinterpret_cast<float4*>(out)[((size_t)b * LOUT + t) * E4 + e] = h;
    }
}

// Kernel 2 (consumer): blocks[b,i,l,:] = fma(xi - xp, s0[b,l,:], xp)
// Grid (83,16,8) = 10624 CTAs, 128 threads (fastest raw config, R3).
// float4 lanes: e4 = tid%32 spans the row, lsub = tid/32 covers 4 l's/step.
// Inner body: 1 LDG.128 + 8 FMA + 2 STG.128 streaming. Everything except the
// S-dependent loads is hoisted before the PDL grid-dependency sync.
__global__ void __launch_bounds__(128, 12)
blocks_kernel(const float* __restrict__ x, float* __restrict__ out) {
    const int b    = blockIdx.y;
    const int tile = blockIdx.x;
    const int zl   = blockIdx.z;
    const int tid  = threadIdx.x;
    const int lsub = tid >> 5;       // 0..3
    const int e4   = tid & 31;       // 0..31

    const float4* __restrict__ x4 = reinterpret_cast<const float4*>(x);

    const int i0 = tile * G;
    const int i1 = i0 + 1;

    // Prologue (independent of g_S) — overlaps with prep via PDL.
    float4 a0 = __ldg(&x4[((size_t)b * LL + (TT + 1 + i0)) * E4 + e4]);
    float4 p0 = __ldg(&x4[((size_t)b * LL + (i0 + 1)) * E4 + e4]);
    float4 a1 = __ldg(&x4[((size_t)b * LL + (TT + 1 + i1)) * E4 + e4]);
    float4 p1 = __ldg(&x4[((size_t)b * LL + (i1 + 1)) * E4 + e4]);
    float4 d0, d1;
    d0.x = a0.x - p0.x; d0.y = a0.y - p0.y; d0.z = a0.z - p0.z; d0.w = a0.w - p0.w;
    d1.x = a1.x - p1.x; d1.y = a1.y - p1.y; d1.z = a1.z - p1.z; d1.w = a1.w - p1.w;

    const int lbeg = zl * LCH;
    const size_t outrow0 = (size_t)b * LOUT + (TT + 1);

    // Hoisted pointers; all advance by 4 rows (4*E4 float4) per iteration.
    const float4* __restrict__ sp =
        reinterpret_cast<const float4*>(g_S) +
        ((size_t)b * LL + lbeg + lsub) * E4 + e4;
    float4* __restrict__ q0 =
        reinterpret_cast<float4*>(out) +
        (outrow0 + (size_t)i0 * LL + lbeg + lsub) * E4 + e4;
    float4* __restrict__ q1 =
        reinterpret_cast<float4*>(out) +
        (outrow0 + (size_t)i1 * LL + lbeg + lsub) * E4 + e4;

    // Wait for prep's triggered completion (S table visible after this).
    cudaGridDependencySynchronize();

#pragma unroll
    for (int it = 0; it < LCH / 4; it++) {
        float4 s = __ldg(sp);
        float4 o0, o1;
        o0.x = fmaf(d0.x, s.x, p0.x);
        o0.y = fmaf(d0.y, s.y, p0.y);
        o0.z = fmaf(d0.z, s.z, p0.z);
        o0.w = fmaf(d0.w, s.w, p0.w);
        o1.x = fmaf(d1.x, s.x, p1.x);
        o1.y = fmaf(d1.y, s.y, p1.y);
        o1.z = fmaf(d1.z, s.z, p1.z);
        o1.w = fmaf(d1.w, s.w, p1.w);
        __stcs(q0, o0);
        __stcs(q1, o1);
        sp += 4 * E4;
        q0 += 4 * E4;
        q1 += 4 * E4;
    }
}

extern "C" void kernel_launch(void* const* d_in, const int* in_sizes, int n_in,
                              void* d_out, int out_size) {
    const float* x  = (const float*)d_in[0];
    const float* W  = (const float*)d_in[1];
    const float* bv = (const float*)d_in[2];
    float* out = (float*)d_out;

    // Producer: 98304 float4s -> 384 blocks of 256.
    prep_kernel<<<(BB * LL * E4 + 255) / 256, 256>>>(x, W, bv, out);

    // Consumer with programmatic dependent launch.
    cudaLaunchAttribute attr[1];
    attr[0].id = cudaLaunchAttributeProgrammaticStreamSerialization;
    attr[0].val.programmaticStreamSerializationAllowed = 1;

    cudaLaunchConfig_t cfg = {};
    cfg.gridDim  = dim3(NI / G, BB, NZ);   // (83, 16, 8) = 10624 CTAs
    cfg.blockDim = dim3(128, 1, 1);
    cfg.dynamicSmemBytes = 0;
    cfg.stream = 0;
    cfg.attrs = attr;
    cfg.numAttrs = 1;

    cudaLaunchKernelEx(&cfg, blocks_kernel, x, out);
}